// round 5
// baseline (speedup 1.0000x reference)
#include <cuda_runtime.h>
#include <math.h>

#define NMAX 50000
#define EMAX 600000
#define F    128
#define NCLSK 40
#define BN_EPS 1e-5f

typedef unsigned long long u64;

__device__ __forceinline__ void ffma2(u64 &d, u64 a, u64 b) {
    asm("fma.rn.f32x2 %0, %1, %2, %0;" : "+l"(d) : "l"(a), "l"(b));
}
__device__ __forceinline__ float2 unpack2(u64 v) {
    float lo, hi;
    asm("mov.b64 {%0, %1}, %2;" : "=f"(lo), "=f"(hi) : "l"(v));
    return make_float2(lo, hi);
}

// ---------------- scratch (device globals; no allocation allowed) ----------------
__device__ float  g_agg [NMAX * F];
__device__ float  g_hlin[NMAX * F];
__device__ int    g_deg [NMAX];
__device__ int    g_off [NMAX];
__device__ int    g_cur [NMAX];
__device__ int    g_csrc[EMAX];
__device__ float  g_invdeg[NMAX];
__device__ float  g_stats[4 * F];   // layer0: [0..255], layer1: [256..511]
__device__ int    g_counter;

// ---------------- histogram (+ zero stats/counter piggyback) ----------------
__global__ void hist_kernel(const int* __restrict__ ei, int ne, int n) {
    if (blockIdx.x == 0) {
        g_stats[threadIdx.x] = 0.f;
        g_stats[256 + threadIdx.x] = 0.f;
        if (threadIdx.x == 0) g_counter = 0;
    }
    int e = blockIdx.x * blockDim.x + threadIdx.x;
    if (e < ne) {
        int d = ei[ne + e];
        if ((unsigned)d < (unsigned)n) atomicAdd(&g_deg[d], 1);
    }
}

// ---------------- one-pass block scan with atomic base ----------------
__global__ __launch_bounds__(256) void scan_blocks_kernel(int n) {
    int tid = threadIdx.x;
    int i = blockIdx.x * 256 + tid;
    int v = (i < n) ? g_deg[i] : 0;

    int incl = v;
    #pragma unroll
    for (int o = 1; o < 32; o <<= 1) {
        int t = __shfl_up_sync(0xffffffffu, incl, o);
        if ((tid & 31) >= o) incl += t;
    }
    __shared__ int wsum[8];
    if ((tid & 31) == 31) wsum[tid >> 5] = incl;
    __syncthreads();
    if (tid < 8) {
        int w = wsum[tid];
        int s = w;
        #pragma unroll
        for (int o = 1; o < 8; o <<= 1) {
            int t = __shfl_up_sync(0x000000ffu, s, o);
            if (tid >= o) s += t;
        }
        wsum[tid] = s - w;
    }
    __syncthreads();
    incl += wsum[tid >> 5];

    __shared__ int base_s;
    if (tid == 255) base_s = atomicAdd(&g_counter, incl);
    __syncthreads();

    if (i < n) {
        int off = base_s + incl - v;
        g_off[i] = off;
        g_cur[i] = off;
        g_invdeg[i] = 1.0f / fmaxf((float)v, 1.0f);
    }
}

__global__ void fill_kernel(const int* __restrict__ ei, int ne, int n) {
    int e = blockIdx.x * blockDim.x + threadIdx.x;
    if (e < ne) {
        int d = ei[ne + e];
        int s = ei[e];
        if ((unsigned)d < (unsigned)n && (unsigned)s < (unsigned)n) {
            int p = atomicAdd(&g_cur[d], 1);
            g_csrc[p] = s;
        }
    }
}

// ------ mean aggregation: one warp per node, 4-way gather ILP (raw feats) ---
__global__ __launch_bounds__(256) void agg_kernel(const float* __restrict__ feat,
                                                  float* __restrict__ outb, int n) {
    int wid  = threadIdx.x >> 5;
    int lane = threadIdx.x & 31;
    int node = blockIdx.x * 8 + wid;
    if (node >= n) return;
    int beg = g_off[node];
    int end = beg + g_deg[node];
    int col = lane * 4;
    float4 a0 = make_float4(0.f,0.f,0.f,0.f), a1 = a0, a2 = a0, a3 = a0;
    int e = beg;
    for (; e + 3 < end; e += 4) {
        int s0 = g_csrc[e], s1 = g_csrc[e+1], s2 = g_csrc[e+2], s3 = g_csrc[e+3];
        float4 v0 = __ldg((const float4*)(feat + (size_t)s0 * F + col));
        float4 v1 = __ldg((const float4*)(feat + (size_t)s1 * F + col));
        float4 v2 = __ldg((const float4*)(feat + (size_t)s2 * F + col));
        float4 v3 = __ldg((const float4*)(feat + (size_t)s3 * F + col));
        a0.x += v0.x; a0.y += v0.y; a0.z += v0.z; a0.w += v0.w;
        a1.x += v1.x; a1.y += v1.y; a1.z += v1.z; a1.w += v1.w;
        a2.x += v2.x; a2.y += v2.y; a2.z += v2.z; a2.w += v2.w;
        a3.x += v3.x; a3.y += v3.y; a3.z += v3.z; a3.w += v3.w;
    }
    for (; e < end; e++) {
        int s0 = g_csrc[e];
        float4 v0 = __ldg((const float4*)(feat + (size_t)s0 * F + col));
        a0.x += v0.x; a0.y += v0.y; a0.z += v0.z; a0.w += v0.w;
    }
    float inv = g_invdeg[node];
    a0.x = (a0.x + a1.x + a2.x + a3.x) * inv;
    a0.y = (a0.y + a1.y + a2.y + a3.y) * inv;
    a0.z = (a0.z + a1.z + a2.z + a3.z) * inv;
    a0.w = (a0.w + a1.w + a2.w + a3.w) * inv;
    *(float4*)(outb + (size_t)node * F + col) = a0;
}

// --- mean aggregation with BN+ReLU per-edge; computes scale/shift itself ---
__global__ __launch_bounds__(256) void agg_bn_kernel(const float* __restrict__ feat,
                                                     const float* __restrict__ g,
                                                     const float* __restrict__ be,
                                                     float* __restrict__ outb, int n) {
    __shared__ float s_sc[F], s_sh[F];
    int tid = threadIdx.x;
    if (tid < F) {
        float mean = g_stats[tid] / (float)n;
        float var  = g_stats[F + tid] / (float)n - mean * mean;
        float sc = g[tid] * rsqrtf(var + BN_EPS);
        s_sc[tid] = sc;
        s_sh[tid] = be[tid] - mean * sc;
    }
    __syncthreads();

    int wid  = tid >> 5;
    int lane = tid & 31;
    int node = blockIdx.x * 8 + wid;
    if (node >= n) return;
    int col = lane * 4;
    float4 sc = *(const float4*)&s_sc[col];
    float4 sh = *(const float4*)&s_sh[col];
    int beg = g_off[node];
    int end = beg + g_deg[node];
    float4 a0 = make_float4(0.f,0.f,0.f,0.f), a1 = a0, a2 = a0, a3 = a0;
    int e = beg;
    for (; e + 3 < end; e += 4) {
        int s0 = g_csrc[e], s1 = g_csrc[e+1], s2 = g_csrc[e+2], s3 = g_csrc[e+3];
        float4 v0 = __ldg((const float4*)(feat + (size_t)s0 * F + col));
        float4 v1 = __ldg((const float4*)(feat + (size_t)s1 * F + col));
        float4 v2 = __ldg((const float4*)(feat + (size_t)s2 * F + col));
        float4 v3 = __ldg((const float4*)(feat + (size_t)s3 * F + col));
        a0.x += fmaxf(v0.x * sc.x + sh.x, 0.f);
        a0.y += fmaxf(v0.y * sc.y + sh.y, 0.f);
        a0.z += fmaxf(v0.z * sc.z + sh.z, 0.f);
        a0.w += fmaxf(v0.w * sc.w + sh.w, 0.f);
        a1.x += fmaxf(v1.x * sc.x + sh.x, 0.f);
        a1.y += fmaxf(v1.y * sc.y + sh.y, 0.f);
        a1.z += fmaxf(v1.z * sc.z + sh.z, 0.f);
        a1.w += fmaxf(v1.w * sc.w + sh.w, 0.f);
        a2.x += fmaxf(v2.x * sc.x + sh.x, 0.f);
        a2.y += fmaxf(v2.y * sc.y + sh.y, 0.f);
        a2.z += fmaxf(v2.z * sc.z + sh.z, 0.f);
        a2.w += fmaxf(v2.w * sc.w + sh.w, 0.f);
        a3.x += fmaxf(v3.x * sc.x + sh.x, 0.f);
        a3.y += fmaxf(v3.y * sc.y + sh.y, 0.f);
        a3.z += fmaxf(v3.z * sc.z + sh.z, 0.f);
        a3.w += fmaxf(v3.w * sc.w + sh.w, 0.f);
    }
    for (; e < end; e++) {
        int s0 = g_csrc[e];
        float4 v0 = __ldg((const float4*)(feat + (size_t)s0 * F + col));
        a0.x += fmaxf(v0.x * sc.x + sh.x, 0.f);
        a0.y += fmaxf(v0.y * sc.y + sh.y, 0.f);
        a0.z += fmaxf(v0.z * sc.z + sh.z, 0.f);
        a0.w += fmaxf(v0.w * sc.w + sh.w, 0.f);
    }
    float inv = g_invdeg[node];
    a0.x = (a0.x + a1.x + a2.x + a3.x) * inv;
    a0.y = (a0.y + a1.y + a2.y + a3.y) * inv;
    a0.z = (a0.z + a1.z + a2.z + a3.z) * inv;
    a0.w = (a0.w + a1.w + a2.w + a3.w) * inv;
    *(float4*)(outb + (size_t)node * F + col) = a0;
}

// --- SGEMM (double-buffered, dup-A smem, pure FFMA2) + fused BN stats -------
#define GBM 128
#define GBK 8
__global__ __launch_bounds__(256) void gemm_stats_kernel(const float* __restrict__ A,
                                                         const float* __restrict__ W,
                                                         const float* __restrict__ bias,
                                                         float* __restrict__ C,
                                                         float* __restrict__ stats, int n) {
    __shared__ float As[2][GBK][2 * GBM];   // duplicated pairs: As[k][2r]=As[k][2r+1]=A[r][k]
    __shared__ float Bs[2][GBK][F];
    __shared__ float s_sum[F];
    __shared__ float s_sq[F];

    int block_row = blockIdx.x * GBM;
    int tid = threadIdx.x;
    int tx = tid & 15, ty = tid >> 4;

    int a_row = tid >> 1;
    int a_k   = (tid & 1) * 4;
    int b_k   = tid >> 5;
    int b_col = (tid & 31) * 4;

    int grow = block_row + a_row;
    bool arow_ok = grow < n;
    const float* aptr = A + (size_t)grow * F + a_k;

    u64 acc2[8][4];
    #pragma unroll
    for (int i = 0; i < 8; i++)
        #pragma unroll
        for (int j = 0; j < 4; j++) acc2[i][j] = 0ULL;

    // prologue: load tile 0
    float4 av = arow_ok ? *(const float4*)aptr : make_float4(0.f,0.f,0.f,0.f);
    float4 bv = *(const float4*)(W + (size_t)b_k * F + b_col);
    *(float2*)&As[0][a_k + 0][2 * a_row] = make_float2(av.x, av.x);
    *(float2*)&As[0][a_k + 1][2 * a_row] = make_float2(av.y, av.y);
    *(float2*)&As[0][a_k + 2][2 * a_row] = make_float2(av.z, av.z);
    *(float2*)&As[0][a_k + 3][2 * a_row] = make_float2(av.w, av.w);
    *(float4*)&Bs[0][b_k][b_col] = bv;
    __syncthreads();

    int buf = 0;
    #pragma unroll
    for (int k0 = 0; k0 < F; k0 += GBK) {
        float4 nav, nbv;
        bool more = (k0 + GBK) < F;
        if (more) {
            nav = arow_ok ? *(const float4*)(aptr + k0 + GBK)
                          : make_float4(0.f,0.f,0.f,0.f);
            nbv = *(const float4*)(W + (size_t)(k0 + GBK + b_k) * F + b_col);
        }
        #pragma unroll
        for (int kk = 0; kk < GBK; kk++) {
            ulonglong2 p0 = *(const ulonglong2*)&As[buf][kk][ty * 16 + 0];
            ulonglong2 p1 = *(const ulonglong2*)&As[buf][kk][ty * 16 + 4];
            ulonglong2 p2 = *(const ulonglong2*)&As[buf][kk][ty * 16 + 8];
            ulonglong2 p3 = *(const ulonglong2*)&As[buf][kk][ty * 16 + 12];
            ulonglong2 b01 = *(const ulonglong2*)&Bs[buf][kk][tx * 8];
            ulonglong2 b23 = *(const ulonglong2*)&Bs[buf][kk][tx * 8 + 4];
            u64 ra[8] = {p0.x, p0.y, p1.x, p1.y, p2.x, p2.y, p3.x, p3.y};
            u64 rb[4] = {b01.x, b01.y, b23.x, b23.y};
            #pragma unroll
            for (int i = 0; i < 8; i++)
                #pragma unroll
                for (int j = 0; j < 4; j++) ffma2(acc2[i][j], ra[i], rb[j]);
        }
        if (more) {
            int nb = buf ^ 1;
            *(float2*)&As[nb][a_k + 0][2 * a_row] = make_float2(nav.x, nav.x);
            *(float2*)&As[nb][a_k + 1][2 * a_row] = make_float2(nav.y, nav.y);
            *(float2*)&As[nb][a_k + 2][2 * a_row] = make_float2(nav.z, nav.z);
            *(float2*)&As[nb][a_k + 3][2 * a_row] = make_float2(nav.w, nav.w);
            *(float4*)&Bs[nb][b_k][b_col] = nbv;
        }
        __syncthreads();
        buf ^= 1;
    }

    float bias_r[8];
    #pragma unroll
    for (int j = 0; j < 8; j++) bias_r[j] = __ldg(&bias[tx * 8 + j]);

    if (tid < F) { s_sum[tid] = 0.f; s_sq[tid] = 0.f; }
    __syncthreads();

    float ps[8], pq[8];
    #pragma unroll
    for (int j = 0; j < 8; j++) { ps[j] = 0.f; pq[j] = 0.f; }

    #pragma unroll
    for (int i = 0; i < 8; i++) {
        int r = block_row + ty * 8 + i;
        if (r < n) {
            float va[8];
            #pragma unroll
            for (int jp = 0; jp < 4; jp++) {
                float2 p = unpack2(acc2[i][jp]);
                va[jp * 2 + 0] = p.x + bias_r[jp * 2 + 0];
                va[jp * 2 + 1] = p.y + bias_r[jp * 2 + 1];
            }
            #pragma unroll
            for (int j = 0; j < 8; j += 4) {
                float4 o = make_float4(va[j], va[j+1], va[j+2], va[j+3]);
                *(float4*)(C + (size_t)r * F + tx * 8 + j) = o;
            }
            #pragma unroll
            for (int j = 0; j < 8; j++) { ps[j] += va[j]; pq[j] += va[j] * va[j]; }
        }
    }
    #pragma unroll
    for (int j = 0; j < 8; j++) {
        atomicAdd(&s_sum[tx * 8 + j], ps[j]);
        atomicAdd(&s_sq[tx * 8 + j], pq[j]);
    }
    __syncthreads();
    if (tid < F) {
        atomicAdd(&stats[tid], s_sum[tid]);
        atomicAdd(&stats[F + tid], s_sq[tid]);
    }
}

// --- classifier: fused BN(scale from raw stats)+ReLU + GEMM + log_softmax ---
__global__ __launch_bounds__(256) void classifier_kernel(const float* __restrict__ H,
                                                         const float* __restrict__ Wc,
                                                         const float* __restrict__ bc,
                                                         const float* __restrict__ g,
                                                         const float* __restrict__ be,
                                                         float* __restrict__ outb, int n) {
    __shared__ float sbuf[6656];
    float* As    = sbuf;           // [8][128]  during k-loop
    float* Ws    = sbuf + 1024;    // [128][40]
    float* s_log = sbuf;           // overlay after k-loop: [128][41]
    float* s_lse = sbuf + 5248;    // [128]
    float* s_sc  = sbuf + 6144;    // [128]  (beyond Ws, persists through k-loop)
    float* s_sh  = sbuf + 6400;    // wait: 6400..6528 — see sizing below

    int tid = threadIdx.x;
    int row0 = blockIdx.x * 128;

    if (tid < F) {
        float mean = g_stats[2 * F + tid] / (float)n;
        float var  = g_stats[3 * F + tid] / (float)n - mean * mean;
        float sc = g[tid] * rsqrtf(var + BN_EPS);
        s_sc[tid] = sc;
        s_sh[tid] = be[tid] - mean * sc;
    }
    for (int idx = tid; idx < F * NCLSK; idx += 256) Ws[idx] = Wc[idx];

    int tx = tid & 7;     // 8 col-groups x 5 classes
    int ty = tid >> 3;    // 32 row-groups x 4 rows

    float acc[4][5];
    #pragma unroll
    for (int i = 0; i < 4; i++)
        #pragma unroll
        for (int j = 0; j < 5; j++) acc[i][j] = 0.f;

    int lrow = tid >> 1;
    int seg  = (tid & 1) * 4;
    int grow = row0 + lrow;
    bool rok = grow < n;
    const float* hp = H + (size_t)grow * F;
    __syncthreads();   // s_sc/s_sh + Ws ready

    for (int k0 = 0; k0 < F; k0 += 8) {
        float4 v = make_float4(0.f,0.f,0.f,0.f);
        if (rok) v = *(const float4*)(hp + k0 + seg);
        float4 sc = *(const float4*)&s_sc[k0 + seg];
        float4 sh = *(const float4*)&s_sh[k0 + seg];
        v.x = fmaxf(v.x * sc.x + sh.x, 0.f);
        v.y = fmaxf(v.y * sc.y + sh.y, 0.f);
        v.z = fmaxf(v.z * sc.z + sh.z, 0.f);
        v.w = fmaxf(v.w * sc.w + sh.w, 0.f);
        As[(seg + 0) * 128 + lrow] = v.x;
        As[(seg + 1) * 128 + lrow] = v.y;
        As[(seg + 2) * 128 + lrow] = v.z;
        As[(seg + 3) * 128 + lrow] = v.w;
        __syncthreads();
        #pragma unroll
        for (int kk = 0; kk < 8; kk++) {
            float ra[4], rb[5];
            #pragma unroll
            for (int i = 0; i < 4; i++) ra[i] = As[kk * 128 + ty * 4 + i];
            #pragma unroll
            for (int j = 0; j < 5; j++) rb[j] = Ws[(k0 + kk) * NCLSK + tx * 5 + j];
            #pragma unroll
            for (int i = 0; i < 4; i++)
                #pragma unroll
                for (int j = 0; j < 5; j++) acc[i][j] += ra[i] * rb[j];
        }
        __syncthreads();
    }

    float bias_r[5];
    #pragma unroll
    for (int j = 0; j < 5; j++) bias_r[j] = __ldg(&bc[tx * 5 + j]);

    #pragma unroll
    for (int i = 0; i < 4; i++)
        #pragma unroll
        for (int j = 0; j < 5; j++)
            s_log[(ty * 4 + i) * 41 + tx * 5 + j] = acc[i][j] + bias_r[j];
    __syncthreads();

    if (tid < 128) {
        float m = -INFINITY;
        #pragma unroll
        for (int c = 0; c < NCLSK; c++) m = fmaxf(m, s_log[tid * 41 + c]);
        float s = 0.f;
        #pragma unroll
        for (int c = 0; c < NCLSK; c++) s += __expf(s_log[tid * 41 + c] - m);
        s_lse[tid] = m + __logf(s);
    }
    __syncthreads();

    int rows = n - row0;
    if (rows > 128) rows = 128;
    int total = rows * NCLSK;
    for (int idx = tid; idx < total; idx += 256) {
        int r = idx / NCLSK;
        int c = idx - r * NCLSK;
        outb[(size_t)(row0 + r) * NCLSK + c] = s_log[r * 41 + c] - s_lse[r];
    }
}

// ---------------- launch ----------------
extern "C" void kernel_launch(void* const* d_in, const int* in_sizes, int n_in,
                              void* d_out, int out_size) {
    const float* x  = (const float*)d_in[0];
    const int*   ei = (const int*)d_in[1];     // int32 (JAX x64 disabled)
    const float* W0 = (const float*)d_in[2];
    const float* b0 = (const float*)d_in[3];
    const float* g0 = (const float*)d_in[4];
    const float* be0 = (const float*)d_in[5];
    const float* W1 = (const float*)d_in[6];
    const float* b1 = (const float*)d_in[7];
    const float* g1 = (const float*)d_in[8];
    const float* be1 = (const float*)d_in[9];
    const float* Wc = (const float*)d_in[10];
    const float* bc = (const float*)d_in[11];
    float* out = (float*)d_out;

    int n  = in_sizes[0] / F;
    int ne = in_sizes[1] / 2;

    void *p_agg, *p_hlin, *p_deg, *p_stats;
    cudaGetSymbolAddress(&p_agg, g_agg);
    cudaGetSymbolAddress(&p_hlin, g_hlin);
    cudaGetSymbolAddress(&p_deg, g_deg);
    cudaGetSymbolAddress(&p_stats, g_stats);
    float* aggp   = (float*)p_agg;
    float* hlinp  = (float*)p_hlin;
    float* stats0 = (float*)p_stats;
    float* stats1 = stats0 + 2 * F;

    // CSR build (shared by both conv layers)
    cudaMemsetAsync(p_deg, 0, (size_t)n * sizeof(int));
    hist_kernel<<<(ne + 255) / 256, 256>>>(ei, ne, n);
    scan_blocks_kernel<<<(n + 255) / 256, 256>>>(n);
    fill_kernel<<<(ne + 255) / 256, 256>>>(ei, ne, n);

    int agg_blocks  = (n + 7) / 8;
    int gemm_blocks = (n + GBM - 1) / GBM;

    // ---- layer 0 ----
    agg_kernel<<<agg_blocks, 256>>>(x, aggp, n);
    gemm_stats_kernel<<<gemm_blocks, 256>>>(aggp, W0, b0, hlinp, stats0, n);

    // ---- layer 1 (BN+ReLU of layer 0 fused into the gather) ----
    agg_bn_kernel<<<agg_blocks, 256>>>(hlinp, g0, be0, aggp, n);
    gemm_stats_kernel<<<gemm_blocks, 256>>>(aggp, W1, b1, hlinp, stats1, n);

    // ---- classifier: fused BN+ReLU + GEMM + log_softmax ----
    classifier_kernel<<<gemm_blocks, 256>>>(hlinp, Wc, bc, g1, be1, out, n);
}

// round 6
// speedup vs baseline: 1.1939x; 1.1939x over previous
#include <cuda_runtime.h>
#include <math.h>

#define NMAX 50000
#define EMAX 600000
#define F    128
#define NCLSK 40
#define BN_EPS 1e-5f

typedef unsigned long long u64;

__device__ __forceinline__ u64 pack_dup(float a) {
    u64 r;
    asm("mov.b64 %0, {%1, %1};" : "=l"(r) : "f"(a));
    return r;
}
__device__ __forceinline__ void ffma2(u64 &d, u64 a, u64 b) {
    asm("fma.rn.f32x2 %0, %1, %2, %0;" : "+l"(d) : "l"(a), "l"(b));
}
__device__ __forceinline__ float2 unpack2(u64 v) {
    float lo, hi;
    asm("mov.b64 {%0, %1}, %2;" : "=f"(lo), "=f"(hi) : "l"(v));
    return make_float2(lo, hi);
}

// ---------------- scratch (device globals; no allocation allowed) ----------------
__device__ float  g_agg [NMAX * F];
__device__ float  g_hlin[NMAX * F];
__device__ int    g_deg [NMAX];
__device__ int    g_off [NMAX];
__device__ int    g_cur [NMAX];
__device__ int    g_csrc[EMAX];
__device__ float  g_invdeg[NMAX];
__device__ float  g_stats[4 * F];   // layer0: [0..255], layer1: [256..511]
__device__ int    g_counter;

// ---------------- histogram (+ zero stats/counter piggyback) ----------------
__global__ void hist_kernel(const int* __restrict__ ei, int ne, int n) {
    if (blockIdx.x == 0) {
        g_stats[threadIdx.x] = 0.f;
        g_stats[256 + threadIdx.x] = 0.f;
        if (threadIdx.x == 0) g_counter = 0;
    }
    int e = blockIdx.x * blockDim.x + threadIdx.x;
    if (e < ne) {
        int d = ei[ne + e];
        if ((unsigned)d < (unsigned)n) atomicAdd(&g_deg[d], 1);
    }
}

// ---------------- one-pass block scan with atomic base ----------------
__global__ __launch_bounds__(256) void scan_blocks_kernel(int n) {
    int tid = threadIdx.x;
    int i = blockIdx.x * 256 + tid;
    int v = (i < n) ? g_deg[i] : 0;

    int incl = v;
    #pragma unroll
    for (int o = 1; o < 32; o <<= 1) {
        int t = __shfl_up_sync(0xffffffffu, incl, o);
        if ((tid & 31) >= o) incl += t;
    }
    __shared__ int wsum[8];
    if ((tid & 31) == 31) wsum[tid >> 5] = incl;
    __syncthreads();
    if (tid < 8) {
        int w = wsum[tid];
        int s = w;
        #pragma unroll
        for (int o = 1; o < 8; o <<= 1) {
            int t = __shfl_up_sync(0x000000ffu, s, o);
            if (tid >= o) s += t;
        }
        wsum[tid] = s - w;
    }
    __syncthreads();
    incl += wsum[tid >> 5];

    __shared__ int base_s;
    if (tid == 255) base_s = atomicAdd(&g_counter, incl);
    __syncthreads();

    if (i < n) {
        int off = base_s + incl - v;
        g_off[i] = off;
        g_cur[i] = off;
        g_invdeg[i] = 1.0f / fmaxf((float)v, 1.0f);
    }
}

__global__ void fill_kernel(const int* __restrict__ ei, int ne, int n) {
    int e = blockIdx.x * blockDim.x + threadIdx.x;
    if (e < ne) {
        int d = ei[ne + e];
        int s = ei[e];
        if ((unsigned)d < (unsigned)n && (unsigned)s < (unsigned)n) {
            int p = atomicAdd(&g_cur[d], 1);
            g_csrc[p] = s;
        }
    }
}

// ---------------- mean aggregation: one warp per node (round-4 proven) -----
__global__ __launch_bounds__(256) void agg_kernel(const float* __restrict__ feat,
                                                  float* __restrict__ outb, int n) {
    int wid  = threadIdx.x >> 5;
    int lane = threadIdx.x & 31;
    int node = blockIdx.x * 8 + wid;
    if (node >= n) return;
    int beg = g_off[node];
    int end = beg + g_deg[node];
    float4 acc  = make_float4(0.f, 0.f, 0.f, 0.f);
    float4 acc2 = make_float4(0.f, 0.f, 0.f, 0.f);
    int e = beg;
    for (; e + 1 < end; e += 2) {
        int s0 = g_csrc[e], s1 = g_csrc[e + 1];
        float4 v0 = *(const float4*)(feat + (size_t)s0 * F + lane * 4);
        float4 v1 = *(const float4*)(feat + (size_t)s1 * F + lane * 4);
        acc.x  += v0.x; acc.y  += v0.y; acc.z  += v0.z; acc.w  += v0.w;
        acc2.x += v1.x; acc2.y += v1.y; acc2.z += v1.z; acc2.w += v1.w;
    }
    if (e < end) {
        int s0 = g_csrc[e];
        float4 v0 = *(const float4*)(feat + (size_t)s0 * F + lane * 4);
        acc.x += v0.x; acc.y += v0.y; acc.z += v0.z; acc.w += v0.w;
    }
    float inv = g_invdeg[node];
    acc.x = (acc.x + acc2.x) * inv; acc.y = (acc.y + acc2.y) * inv;
    acc.z = (acc.z + acc2.z) * inv; acc.w = (acc.w + acc2.w) * inv;
    *(float4*)(outb + (size_t)node * F + lane * 4) = acc;
}

// --- mean aggregation with BN+ReLU per-edge; computes scale/shift itself ---
__global__ __launch_bounds__(256) void agg_bn_kernel(const float* __restrict__ feat,
                                                     const float* __restrict__ g,
                                                     const float* __restrict__ be,
                                                     float* __restrict__ outb, int n) {
    __shared__ float s_sc[F], s_sh[F];
    int tid = threadIdx.x;
    if (tid < F) {
        float mean = g_stats[tid] / (float)n;
        float var  = g_stats[F + tid] / (float)n - mean * mean;
        float sck = g[tid] * rsqrtf(var + BN_EPS);
        s_sc[tid] = sck;
        s_sh[tid] = be[tid] - mean * sck;
    }
    __syncthreads();

    int wid  = tid >> 5;
    int lane = tid & 31;
    int node = blockIdx.x * 8 + wid;
    if (node >= n) return;
    float4 sc = *(const float4*)&s_sc[lane * 4];
    float4 sh = *(const float4*)&s_sh[lane * 4];
    int beg = g_off[node];
    int end = beg + g_deg[node];
    float4 acc  = make_float4(0.f, 0.f, 0.f, 0.f);
    float4 acc2 = make_float4(0.f, 0.f, 0.f, 0.f);
    int e = beg;
    for (; e + 1 < end; e += 2) {
        int s0 = g_csrc[e], s1 = g_csrc[e + 1];
        float4 v0 = *(const float4*)(feat + (size_t)s0 * F + lane * 4);
        float4 v1 = *(const float4*)(feat + (size_t)s1 * F + lane * 4);
        acc.x  += fmaxf(v0.x * sc.x + sh.x, 0.f);
        acc.y  += fmaxf(v0.y * sc.y + sh.y, 0.f);
        acc.z  += fmaxf(v0.z * sc.z + sh.z, 0.f);
        acc.w  += fmaxf(v0.w * sc.w + sh.w, 0.f);
        acc2.x += fmaxf(v1.x * sc.x + sh.x, 0.f);
        acc2.y += fmaxf(v1.y * sc.y + sh.y, 0.f);
        acc2.z += fmaxf(v1.z * sc.z + sh.z, 0.f);
        acc2.w += fmaxf(v1.w * sc.w + sh.w, 0.f);
    }
    if (e < end) {
        int s0 = g_csrc[e];
        float4 v0 = *(const float4*)(feat + (size_t)s0 * F + lane * 4);
        acc.x += fmaxf(v0.x * sc.x + sh.x, 0.f);
        acc.y += fmaxf(v0.y * sc.y + sh.y, 0.f);
        acc.z += fmaxf(v0.z * sc.z + sh.z, 0.f);
        acc.w += fmaxf(v0.w * sc.w + sh.w, 0.f);
    }
    float inv = g_invdeg[node];
    acc.x = (acc.x + acc2.x) * inv; acc.y = (acc.y + acc2.y) * inv;
    acc.z = (acc.z + acc2.z) * inv; acc.w = (acc.w + acc2.w) * inv;
    *(float4*)(outb + (size_t)node * F + lane * 4) = acc;
}

// -------- SGEMM (round-4 proven: double-buffered, pack_dup f32x2) + stats ---
#define GBM 128
#define GBK 8
__global__ __launch_bounds__(256) void gemm_stats_kernel(const float* __restrict__ A,
                                                         const float* __restrict__ W,
                                                         const float* __restrict__ bias,
                                                         float* __restrict__ C,
                                                         float* __restrict__ stats, int n) {
    __shared__ float As[2][GBK][GBM];
    __shared__ float Bs[2][GBK][F];
    __shared__ float s_sum[F];
    __shared__ float s_sq[F];

    int block_row = blockIdx.x * GBM;
    int tid = threadIdx.x;
    int tx = tid & 15, ty = tid >> 4;

    int a_row = tid >> 1;
    int a_k   = (tid & 1) * 4;
    int b_k   = tid >> 5;
    int b_col = (tid & 31) * 4;

    int grow = block_row + a_row;
    bool arow_ok = grow < n;
    const float* aptr = A + (size_t)grow * F + a_k;

    u64 acc2[8][4];
    #pragma unroll
    for (int i = 0; i < 8; i++)
        #pragma unroll
        for (int j = 0; j < 4; j++) acc2[i][j] = 0ULL;

    float4 av = arow_ok ? *(const float4*)aptr : make_float4(0.f,0.f,0.f,0.f);
    float4 bv = *(const float4*)(W + (size_t)b_k * F + b_col);
    As[0][a_k + 0][a_row] = av.x;
    As[0][a_k + 1][a_row] = av.y;
    As[0][a_k + 2][a_row] = av.z;
    As[0][a_k + 3][a_row] = av.w;
    *(float4*)&Bs[0][b_k][b_col] = bv;
    __syncthreads();

    int buf = 0;
    #pragma unroll
    for (int k0 = 0; k0 < F; k0 += GBK) {
        float4 nav, nbv;
        bool more = (k0 + GBK) < F;
        if (more) {
            nav = arow_ok ? *(const float4*)(aptr + k0 + GBK)
                          : make_float4(0.f,0.f,0.f,0.f);
            nbv = *(const float4*)(W + (size_t)(k0 + GBK + b_k) * F + b_col);
        }
        #pragma unroll
        for (int kk = 0; kk < GBK; kk++) {
            float4 a0 = *(const float4*)&As[buf][kk][ty * 8];
            float4 a1 = *(const float4*)&As[buf][kk][ty * 8 + 4];
            ulonglong2 b01 = *(const ulonglong2*)&Bs[buf][kk][tx * 8];
            ulonglong2 b23 = *(const ulonglong2*)&Bs[buf][kk][tx * 8 + 4];
            u64 rb[4] = {b01.x, b01.y, b23.x, b23.y};
            u64 ra[8] = {pack_dup(a0.x), pack_dup(a0.y), pack_dup(a0.z), pack_dup(a0.w),
                         pack_dup(a1.x), pack_dup(a1.y), pack_dup(a1.z), pack_dup(a1.w)};
            #pragma unroll
            for (int i = 0; i < 8; i++)
                #pragma unroll
                for (int j = 0; j < 4; j++) ffma2(acc2[i][j], ra[i], rb[j]);
        }
        if (more) {
            int nb = buf ^ 1;
            As[nb][a_k + 0][a_row] = nav.x;
            As[nb][a_k + 1][a_row] = nav.y;
            As[nb][a_k + 2][a_row] = nav.z;
            As[nb][a_k + 3][a_row] = nav.w;
            *(float4*)&Bs[nb][b_k][b_col] = nbv;
        }
        __syncthreads();
        buf ^= 1;
    }

    float bias_r[8];
    #pragma unroll
    for (int j = 0; j < 8; j++) bias_r[j] = __ldg(&bias[tx * 8 + j]);

    if (tid < F) { s_sum[tid] = 0.f; s_sq[tid] = 0.f; }
    __syncthreads();

    float ps[8], pq[8];
    #pragma unroll
    for (int j = 0; j < 8; j++) { ps[j] = 0.f; pq[j] = 0.f; }

    #pragma unroll
    for (int i = 0; i < 8; i++) {
        int r = block_row + ty * 8 + i;
        if (r < n) {
            float va[8];
            #pragma unroll
            for (int jp = 0; jp < 4; jp++) {
                float2 p = unpack2(acc2[i][jp]);
                va[jp * 2 + 0] = p.x + bias_r[jp * 2 + 0];
                va[jp * 2 + 1] = p.y + bias_r[jp * 2 + 1];
            }
            #pragma unroll
            for (int j = 0; j < 8; j += 4) {
                float4 o = make_float4(va[j], va[j+1], va[j+2], va[j+3]);
                *(float4*)(C + (size_t)r * F + tx * 8 + j) = o;
            }
            #pragma unroll
            for (int j = 0; j < 8; j++) { ps[j] += va[j]; pq[j] += va[j] * va[j]; }
        }
    }
    #pragma unroll
    for (int j = 0; j < 8; j++) {
        atomicAdd(&s_sum[tx * 8 + j], ps[j]);
        atomicAdd(&s_sq[tx * 8 + j], pq[j]);
    }
    __syncthreads();
    if (tid < F) {
        atomicAdd(&stats[tid], s_sum[tid]);
        atomicAdd(&stats[F + tid], s_sq[tid]);
    }
}

// --- classifier: fused BN(from raw stats)+ReLU + GEMM + log_softmax --------
__global__ __launch_bounds__(256) void classifier_kernel(const float* __restrict__ H,
                                                         const float* __restrict__ Wc,
                                                         const float* __restrict__ bc,
                                                         const float* __restrict__ g,
                                                         const float* __restrict__ be,
                                                         float* __restrict__ outb, int n) {
    __shared__ float sbuf[6656];
    float* As    = sbuf;           // [8][128]  during k-loop
    float* Ws    = sbuf + 1024;    // [128][40]
    float* s_log = sbuf;           // overlay after k-loop: [128][41]
    float* s_lse = sbuf + 5248;    // [128]
    float* s_sc  = sbuf + 6144;    // [128]
    float* s_sh  = sbuf + 6272;    // [128]

    int tid = threadIdx.x;
    int row0 = blockIdx.x * 128;

    if (tid < F) {
        float mean = g_stats[2 * F + tid] / (float)n;
        float var  = g_stats[3 * F + tid] / (float)n - mean * mean;
        float sck = g[tid] * rsqrtf(var + BN_EPS);
        s_sc[tid] = sck;
        s_sh[tid] = be[tid] - mean * sck;
    }
    for (int idx = tid; idx < F * NCLSK; idx += 256) Ws[idx] = Wc[idx];

    int tx = tid & 7;     // 8 col-groups x 5 classes
    int ty = tid >> 3;    // 32 row-groups x 4 rows

    float acc[4][5];
    #pragma unroll
    for (int i = 0; i < 4; i++)
        #pragma unroll
        for (int j = 0; j < 5; j++) acc[i][j] = 0.f;

    int lrow = tid >> 1;
    int seg  = (tid & 1) * 4;
    int grow = row0 + lrow;
    bool rok = grow < n;
    const float* hp = H + (size_t)grow * F;
    __syncthreads();   // s_sc/s_sh + Ws ready

    for (int k0 = 0; k0 < F; k0 += 8) {
        float4 v = make_float4(0.f,0.f,0.f,0.f);
        if (rok) v = *(const float4*)(hp + k0 + seg);
        float4 sc = *(const float4*)&s_sc[k0 + seg];
        float4 sh = *(const float4*)&s_sh[k0 + seg];
        v.x = fmaxf(v.x * sc.x + sh.x, 0.f);
        v.y = fmaxf(v.y * sc.y + sh.y, 0.f);
        v.z = fmaxf(v.z * sc.z + sh.z, 0.f);
        v.w = fmaxf(v.w * sc.w + sh.w, 0.f);
        As[(seg + 0) * 128 + lrow] = v.x;
        As[(seg + 1) * 128 + lrow] = v.y;
        As[(seg + 2) * 128 + lrow] = v.z;
        As[(seg + 3) * 128 + lrow] = v.w;
        __syncthreads();
        #pragma unroll
        for (int kk = 0; kk < 8; kk++) {
            float ra[4], rb[5];
            #pragma unroll
            for (int i = 0; i < 4; i++) ra[i] = As[kk * 128 + ty * 4 + i];
            #pragma unroll
            for (int j = 0; j < 5; j++) rb[j] = Ws[(k0 + kk) * NCLSK + tx * 5 + j];
            #pragma unroll
            for (int i = 0; i < 4; i++)
                #pragma unroll
                for (int j = 0; j < 5; j++) acc[i][j] += ra[i] * rb[j];
        }
        __syncthreads();
    }

    float bias_r[5];
    #pragma unroll
    for (int j = 0; j < 5; j++) bias_r[j] = __ldg(&bc[tx * 5 + j]);

    #pragma unroll
    for (int i = 0; i < 4; i++)
        #pragma unroll
        for (int j = 0; j < 5; j++)
            s_log[(ty * 4 + i) * 41 + tx * 5 + j] = acc[i][j] + bias_r[j];
    __syncthreads();

    if (tid < 128) {
        float m = -INFINITY;
        #pragma unroll
        for (int c = 0; c < NCLSK; c++) m = fmaxf(m, s_log[tid * 41 + c]);
        float s = 0.f;
        #pragma unroll
        for (int c = 0; c < NCLSK; c++) s += __expf(s_log[tid * 41 + c] - m);
        s_lse[tid] = m + __logf(s);
    }
    __syncthreads();

    int rows = n - row0;
    if (rows > 128) rows = 128;
    int total = rows * NCLSK;
    for (int idx = tid; idx < total; idx += 256) {
        int r = idx / NCLSK;
        int c = idx - r * NCLSK;
        outb[(size_t)(row0 + r) * NCLSK + c] = s_log[r * 41 + c] - s_lse[r];
    }
}

// ---------------- launch ----------------
extern "C" void kernel_launch(void* const* d_in, const int* in_sizes, int n_in,
                              void* d_out, int out_size) {
    const float* x  = (const float*)d_in[0];
    const int*   ei = (const int*)d_in[1];     // int32 (JAX x64 disabled)
    const float* W0 = (const float*)d_in[2];
    const float* b0 = (const float*)d_in[3];
    const float* g0 = (const float*)d_in[4];
    const float* be0 = (const float*)d_in[5];
    const float* W1 = (const float*)d_in[6];
    const float* b1 = (const float*)d_in[7];
    const float* g1 = (const float*)d_in[8];
    const float* be1 = (const float*)d_in[9];
    const float* Wc = (const float*)d_in[10];
    const float* bc = (const float*)d_in[11];
    float* out = (float*)d_out;

    int n  = in_sizes[0] / F;
    int ne = in_sizes[1] / 2;

    void *p_agg, *p_hlin, *p_deg, *p_stats;
    cudaGetSymbolAddress(&p_agg, g_agg);
    cudaGetSymbolAddress(&p_hlin, g_hlin);
    cudaGetSymbolAddress(&p_deg, g_deg);
    cudaGetSymbolAddress(&p_stats, g_stats);
    float* aggp   = (float*)p_agg;
    float* hlinp  = (float*)p_hlin;
    float* stats0 = (float*)p_stats;
    float* stats1 = stats0 + 2 * F;

    // CSR build (shared by both conv layers)
    cudaMemsetAsync(p_deg, 0, (size_t)n * sizeof(int));
    hist_kernel<<<(ne + 255) / 256, 256>>>(ei, ne, n);
    scan_blocks_kernel<<<(n + 255) / 256, 256>>>(n);
    fill_kernel<<<(ne + 255) / 256, 256>>>(ei, ne, n);

    int agg_blocks  = (n + 7) / 8;
    int gemm_blocks = (n + GBM - 1) / GBM;

    // ---- layer 0 ----
    agg_kernel<<<agg_blocks, 256>>>(x, aggp, n);
    gemm_stats_kernel<<<gemm_blocks, 256>>>(aggp, W0, b0, hlinp, stats0, n);

    // ---- layer 1 (BN+ReLU of layer 0 fused into the gather) ----
    agg_bn_kernel<<<agg_blocks, 256>>>(hlinp, g0, be0, aggp, n);
    gemm_stats_kernel<<<gemm_blocks, 256>>>(aggp, W1, b1, hlinp, stats1, n);

    // ---- classifier: fused BN+ReLU + GEMM + log_softmax ----
    classifier_kernel<<<gemm_blocks, 256>>>(hlinp, Wc, bc, g1, be1, out, n);
}